// round 14
// baseline (speedup 1.0000x reference)
#include <cuda_runtime.h>
#include <cuda_bf16.h>
#include <math.h>
#include <cstdint>

#define B_ 256
#define H_ 1024
#define P_ 3
#define S_ 512
#define EPSBN 1e-5f
#define NPART 8
#define BCH 32

// ---------------- static device scratch ----------------
__device__ float g_gp[B_ * 3 * H_];
__device__ float g_gi[2 * B_ * 3 * H_];
__device__ float g_gh[2 * B_ * 3 * H_];
__device__ float g_hc[B_ * 2 * H_];        // [h | ctx] fp32
__device__ float g_qp[8 * B_ * H_];
__device__ float g_qn[B_ * H_];
__device__ float g_yp[8 * B_ * H_];
__device__ float g_y[B_ * H_];
__device__ float g_bns[BCH * H_];
__device__ float g_bns2[BCH * H_];
__device__ float g_mu[H_];
__device__ float g_rstd[H_];
__device__ float g_pm[B_ * NPART];
__device__ float g_pl[B_ * NPART];
__device__ float g_pacc[B_ * NPART * H_];
__device__ float g_e[B_ * S_];

// =====================================================================
// helpers
// =====================================================================
__device__ __forceinline__ uint32_t split2u(float x, float y, uint32_t& lo_bits)
{
    __nv_bfloat16 hx = __float2bfloat16(x);
    __nv_bfloat16 hy = __float2bfloat16(y);
    __nv_bfloat16 lx = __float2bfloat16(x - __bfloat162float(hx));
    __nv_bfloat16 ly = __float2bfloat16(y - __bfloat162float(hy));
    __nv_bfloat162 h = __halves2bfloat162(hx, hy);
    __nv_bfloat162 l = __halves2bfloat162(lx, ly);
    lo_bits = *reinterpret_cast<uint32_t*>(&l);
    return *reinterpret_cast<uint32_t*>(&h);
}

__device__ __forceinline__ uint32_t smem_u32(const void* p)
{
    uint32_t a;
    asm("{ .reg .u64 t; cvta.to.shared.u64 t, %1; cvt.u32.u64 %0, t; }"
        : "=r"(a) : "l"(p));
    return a;
}

__device__ __forceinline__ void ldsm_x4(uint32_t* r, uint32_t addr)
{
    asm volatile("ldmatrix.sync.aligned.m8n8.x4.shared.b16 {%0,%1,%2,%3}, [%4];"
        : "=r"(r[0]), "=r"(r[1]), "=r"(r[2]), "=r"(r[3]) : "r"(addr));
}

__device__ __forceinline__ void mma_bf16(float* d, const uint32_t* a, const uint32_t* b)
{
    asm volatile(
        "mma.sync.aligned.m16n8k16.row.col.f32.bf16.bf16.f32 "
        "{%0,%1,%2,%3}, {%4,%5,%6,%7}, {%8,%9}, {%0,%1,%2,%3};"
        : "+f"(d[0]), "+f"(d[1]), "+f"(d[2]), "+f"(d[3])
        : "r"(a[0]), "r"(a[1]), "r"(a[2]), "r"(a[3]), "r"(b[0]), "r"(b[1]));
}

#define CP_ASYNC16(saddr, gptr) \
    asm volatile("cp.async.cg.shared.global [%0], [%1], 16;" \
        :: "r"(saddr), "l"(gptr) : "memory")
#define CP_COMMIT() asm volatile("cp.async.commit_group;" ::: "memory")
#define CP_WAIT0()  asm volatile("cp.async.wait_group 0;" ::: "memory")

// =====================================================================
// mma GEMM core with fused fp32->bf16 hi/lo conversion in staging.
// 128x64 C tile, 128 thr (4 warps, each 64x32), BK=32, single buffer.
// A fp32 (rows 16B-aligned), W fp32 (ldw, +woff; walign=1 if 16B-aligned)
// =====================================================================
#define RST 40
#define A_RSZ (128 * RST * 2)       // 10240
#define B_RSZ (64 * RST * 2)        // 5120
#define GEMM_SMEM (2 * A_RSZ + 2 * B_RSZ)   // 30720

__device__ void mma_core(
    const float* __restrict__ A, int lda,
    const float* __restrict__ W, int ldw, int woff, int walign,
    float* __restrict__ C, int ldc,
    int nchunks, int kstart, int bm0, int bn0)
{
    extern __shared__ unsigned char sm[];
    const uint32_t sb = smem_u32(sm);
    const uint32_t aHi = sb, aLo = sb + A_RSZ;
    const uint32_t bHi = sb + 2 * A_RSZ, bLo = bHi + B_RSZ;

    const int tid = threadIdx.x;
    const int wid = tid >> 5, lane = tid & 31;
    const int wm = (wid >> 1) * 64;
    const int wn = (wid & 1) * 32;

    const int rs = tid >> 2;            // 0..31
    const int cs = (tid & 3) * 8;       // 0,8,16,24
    const uint32_t so = (uint32_t)(rs * RST + cs) * 2;
    const uint32_t sstep = (uint32_t)(32 * RST * 2);

    const float* Abase = A + (size_t)(bm0 + rs) * lda + kstart + cs;
    const float* Wbase = W + (size_t)(bn0 + rs) * ldw + woff + kstart + cs;

    float acc[4][4][4];
#pragma unroll
    for (int i = 0; i < 4; i++)
#pragma unroll
        for (int j = 0; j < 4; j++)
#pragma unroll
            for (int k = 0; k < 4; k++) acc[i][j][k] = 0.f;

    const uint32_t a_off = (uint32_t)(((wm + (lane & 15)) * RST + (lane >> 4) * 8) * 2);
    const uint32_t b_off = (uint32_t)(((wn + ((lane >> 4) << 3) + (lane & 7)) * RST
                                       + ((lane >> 3) & 1) * 8) * 2);
    const uint32_t mstep = (uint32_t)(16 * RST * 2);

    for (int t = 0; t < nchunks; t++) {
        const int kb = t * 32;

        // ---- batched loads (MLP high), then convert + STS ----
        float fa[4][8];
#pragma unroll
        for (int i = 0; i < 4; i++) {
            const float* p = Abase + (size_t)(32 * i) * lda + kb;
            *(float4*)&fa[i][0] = *(const float4*)p;
            *(float4*)&fa[i][4] = *(const float4*)(p + 4);
        }
        float fb[2][8];
        if (walign) {
#pragma unroll
            for (int i = 0; i < 2; i++) {
                const float* p = Wbase + (size_t)(32 * i) * ldw + kb;
                *(float4*)&fb[i][0] = *(const float4*)p;
                *(float4*)&fb[i][4] = *(const float4*)(p + 4);
            }
        } else {
#pragma unroll
            for (int i = 0; i < 2; i++) {
                const float* p = Wbase + (size_t)(32 * i) * ldw + kb;
#pragma unroll
                for (int j = 0; j < 8; j++) fb[i][j] = p[j];
            }
        }

#pragma unroll
        for (int i = 0; i < 4; i++) {
            uint4 hv, lv;
            hv.x = split2u(fa[i][0], fa[i][1], lv.x);
            hv.y = split2u(fa[i][2], fa[i][3], lv.y);
            hv.z = split2u(fa[i][4], fa[i][5], lv.z);
            hv.w = split2u(fa[i][6], fa[i][7], lv.w);
            asm volatile("st.shared.v4.b32 [%0], {%1,%2,%3,%4};"
                :: "r"(aHi + so + i * sstep), "r"(hv.x), "r"(hv.y), "r"(hv.z), "r"(hv.w));
            asm volatile("st.shared.v4.b32 [%0], {%1,%2,%3,%4};"
                :: "r"(aLo + so + i * sstep), "r"(lv.x), "r"(lv.y), "r"(lv.z), "r"(lv.w));
        }
#pragma unroll
        for (int i = 0; i < 2; i++) {
            uint4 hv, lv;
            hv.x = split2u(fb[i][0], fb[i][1], lv.x);
            hv.y = split2u(fb[i][2], fb[i][3], lv.y);
            hv.z = split2u(fb[i][4], fb[i][5], lv.z);
            hv.w = split2u(fb[i][6], fb[i][7], lv.w);
            asm volatile("st.shared.v4.b32 [%0], {%1,%2,%3,%4};"
                :: "r"(bHi + so + i * sstep), "r"(hv.x), "r"(hv.y), "r"(hv.z), "r"(hv.w));
            asm volatile("st.shared.v4.b32 [%0], {%1,%2,%3,%4};"
                :: "r"(bLo + so + i * sstep), "r"(lv.x), "r"(lv.y), "r"(lv.z), "r"(lv.w));
        }
        __syncthreads();

        // ---- compute (identical fragment math to proven version) ----
#pragma unroll
        for (int kt = 0; kt < 2; kt++) {
            const uint32_t ko = (uint32_t)(kt * 16 * 2);
            uint32_t bh0[4], bh1[4], bl0[4], bl1[4];
            ldsm_x4(bh0, bHi + b_off + ko);
            ldsm_x4(bh1, bHi + b_off + ko + mstep);
            ldsm_x4(bl0, bLo + b_off + ko);
            ldsm_x4(bl1, bLo + b_off + ko + mstep);

#pragma unroll
            for (int mt = 0; mt < 4; mt++) {
                uint32_t ah[4], al[4];
                ldsm_x4(ah, aHi + a_off + ko + mt * mstep);
                ldsm_x4(al, aLo + a_off + ko + mt * mstep);
#pragma unroll
                for (int nn = 0; nn < 4; nn++) {
                    const uint32_t* BH = ((nn < 2) ? bh0 : bh1) + (nn & 1) * 2;
                    const uint32_t* BL = ((nn < 2) ? bl0 : bl1) + (nn & 1) * 2;
                    float* d = acc[mt][nn];
                    mma_bf16(d, ah, BH);
                    mma_bf16(d, ah, BL);
                    mma_bf16(d, al, BH);
                }
            }
        }
        __syncthreads();
    }

    const int er = lane >> 2;
    const int ec = (lane & 3) * 2;
#pragma unroll
    for (int mt = 0; mt < 4; mt++) {
#pragma unroll
        for (int nn = 0; nn < 4; nn++) {
            const int row = bm0 + wm + mt * 16 + er;
            const int col = bn0 + wn + nn * 8 + ec;
            float* d = acc[mt][nn];
            *(float2*)&C[(size_t)row * ldc + col]       = make_float2(d[0], d[1]);
            *(float2*)&C[(size_t)(row + 8) * ldc + col] = make_float2(d[2], d[3]);
        }
    }
}

// gi/gh, each split-K 2: z = which*2 + khalf.  grid (48, 2, 4) = 384 CTAs.
__global__ void __launch_bounds__(128) gemm_dual(
    const float* __restrict__ ctx, const float* __restrict__ h0,
    const float* __restrict__ Wih, const float* __restrict__ Whh)
{
    const int bm0 = blockIdx.y * 128, bn0 = blockIdx.x * 64;
    const int half = blockIdx.z & 1;
    const int which = blockIdx.z >> 1;
    if (which == 0)
        mma_core(ctx, H_, Wih, H_ + P_, P_, 0,
                 g_gi + (size_t)half * B_ * 3 * H_, 3 * H_,
                 16, half * 512, bm0, bn0);
    else
        mma_core(h0, H_, Whh, H_, 0, 1,
                 g_gh + (size_t)half * B_ * 3 * H_, 3 * H_,
                 16, half * 512, bm0, bn0);
}

// q partials: split-K 8 (kchunk 128), grid (16, 2, 8) = 256 CTAs
__global__ void __launch_bounds__(128) gemm_q(const float* __restrict__ attn_W)
{
    const int z = blockIdx.z;
    mma_core(g_hc, 2 * H_, attn_W, H_, 0, 1,
             g_qp + (size_t)z * B_ * H_, H_,
             4, z * 128, blockIdx.y * 128, blockIdx.x * 64);
}

// y partials: split-K 8 (kchunk 256), grid (16, 2, 8) = 256 CTAs
__global__ void __launch_bounds__(128) gemm_y(const float* __restrict__ W1)
{
    const int z = blockIdx.z;
    mma_core(g_hc, 2 * H_, W1, 2 * H_, 0, 1,
             g_yp + (size_t)z * B_ * H_, H_,
             8, z * 256, blockIdx.y * 128, blockIdx.x * 64);
}

// =====================================================================
// gp[b][n] = palette[b] . Wih[n][0:3]  (192 blocks: 12 n-chunks x 16 b)
// =====================================================================
__global__ void gp_kernel(const float* __restrict__ palette,
                          const float* __restrict__ Wih)
{
    const int nc = blockIdx.x % 12;
    const int bc = blockIdx.x / 12;
    __shared__ float w0[256], w1[256], w2[256];
    const int n = nc * 256 + threadIdx.x;
    w0[threadIdx.x] = Wih[(size_t)n * (H_ + P_) + 0];
    w1[threadIdx.x] = Wih[(size_t)n * (H_ + P_) + 1];
    w2[threadIdx.x] = Wih[(size_t)n * (H_ + P_) + 2];
    __syncthreads();
    for (int b = bc * 16; b < bc * 16 + 16; b++) {
        float p0 = palette[b * 3 + 0], p1 = palette[b * 3 + 1], p2 = palette[b * 3 + 2];
        g_gp[(size_t)b * 3 * H_ + n] =
            p0 * w0[threadIdx.x] + p1 * w1[threadIdx.x] + p2 * w2[threadIdx.x];
    }
}

// =====================================================================
// GRU gates: sums 2 split-K partials; writes fp32 h to g_hc + out_h
// =====================================================================
__global__ void gru_gate_kernel(const float* __restrict__ h0,
                                const float* __restrict__ bih,
                                const float* __restrict__ bhh,
                                float* __restrict__ out_h)
{
    const size_t PART = (size_t)B_ * 3 * H_;
    int idx = blockIdx.x * 256 + threadIdx.x;
    int b = idx >> 10;
    int j = idx & (H_ - 1);
    size_t base = (size_t)b * (3 * H_);
    float gir = g_gi[base + j]          + g_gi[PART + base + j]          + g_gp[base + j]          + bih[j];
    float giz = g_gi[base + H_ + j]     + g_gi[PART + base + H_ + j]     + g_gp[base + H_ + j]     + bih[H_ + j];
    float gin = g_gi[base + 2 * H_ + j] + g_gi[PART + base + 2 * H_ + j] + g_gp[base + 2 * H_ + j] + bih[2 * H_ + j];
    float ghr = g_gh[base + j]          + g_gh[PART + base + j]          + bhh[j];
    float ghz = g_gh[base + H_ + j]     + g_gh[PART + base + H_ + j]     + bhh[H_ + j];
    float ghn = g_gh[base + 2 * H_ + j] + g_gh[PART + base + 2 * H_ + j] + bhh[2 * H_ + j];
    float r = 1.f / (1.f + __expf(-(gir + ghr)));
    float z = 1.f / (1.f + __expf(-(giz + ghz)));
    float n = tanhf(gin + r * ghn);
    float h = (1.f - z) * n + z * h0[idx];
    g_hc[(size_t)b * (2 * H_) + j] = h;
    if (out_h) out_h[idx] = h;
}

// =====================================================================
// q reduce + L2 normalize
// =====================================================================
__global__ void q_reduce_kernel(const float* __restrict__ attn_b)
{
    const int b = blockIdx.x, tid = threadIdx.x;
    const int warp = tid >> 5, lane = tid & 31;
    __shared__ float red[8];
    float qv[4];
    float ss = 0.f;
#pragma unroll
    for (int c = 0; c < 4; c++) {
        int h = tid + 256 * c;
        size_t o = (size_t)b * H_ + h;
        float q = attn_b[h];
#pragma unroll
        for (int z = 0; z < 8; z++) q += g_qp[(size_t)z * B_ * H_ + o];
        qv[c] = q;
        ss += q * q;
    }
#pragma unroll
    for (int o = 16; o; o >>= 1) ss += __shfl_xor_sync(0xffffffffu, ss, o);
    if (lane == 0) red[warp] = ss;
    __syncthreads();
    float tot = red[0] + red[1] + red[2] + red[3] + red[4] + red[5] + red[6] + red[7];
    float qinv = rsqrtf(tot);
#pragma unroll
    for (int c = 0; c < 4; c++)
        g_qn[(size_t)b * H_ + tid + 256 * c] = qv[c] * qinv;
}

// =====================================================================
// Attention: NPART seq partitions, 2-buffer cp.async (proven version)
// =====================================================================
#define ATT_SMEM ((1024 + 2 * 8 * 1024) * 4)

__device__ __forceinline__ void att_issue(
    const float* __restrict__ enc, int b, int s0, int rows,
    float* tiles, uint32_t tiles_sb, int buf, int tid)
{
    const int row = tid >> 5;
    const int seg = (tid & 31) * 32;
    float* dstf = tiles + buf * 8192 + row * 1024 + seg;
    if (row < rows) {
        const float* src = enc + ((size_t)(s0 + row) * B_ + b) * H_ + seg;
        const uint32_t dsa = tiles_sb + (uint32_t)(buf * 8192 + row * 1024 + seg) * 4;
#pragma unroll
        for (int j = 0; j < 8; j++)
            CP_ASYNC16(dsa + j * 16, src + j * 4);
    } else {
#pragma unroll
        for (int j = 0; j < 8; j++)
            *(float4*)(dstf + j * 4) = make_float4(0.f, 0.f, 0.f, 0.f);
    }
    CP_COMMIT();
}

__global__ void __launch_bounds__(256) attn_part_kernel(
    const float* __restrict__ enc,
    const int* __restrict__ lens)
{
    const int b = blockIdx.x;
    const int p = blockIdx.y;
    const int tid = threadIdx.x;
    const int warp = tid >> 5, lane = tid & 31;

    extern __shared__ float dyn[];
    float* q_s = dyn;
    float* tiles = dyn + 1024;
    const uint32_t tiles_sb = smem_u32(tiles);
    __shared__ float e_chunk[8];

#pragma unroll
    for (int c = 0; c < 4; c++)
        q_s[tid + 256 * c] = g_qn[(size_t)b * H_ + tid + 256 * c];
    __syncthreads();

    const int len = lens[b];
    const int sbg = p * (S_ / NPART);
    const int se = min(len, sbg + (S_ / NPART));

    float m = -INFINITY, l = 0.f;
    float acc[4] = {0.f, 0.f, 0.f, 0.f};

    if (sbg < se) att_issue(enc, b, sbg, min(8, se - sbg), tiles, tiles_sb, 0, tid);

    int buf = 0;
    for (int s0 = sbg; s0 < se; s0 += 8) {
        const int rows = min(8, se - s0);
        CP_WAIT0();
        __syncthreads();
        if (s0 + 8 < se)
            att_issue(enc, b, s0 + 8, min(8, se - s0 - 8), tiles, tiles_sb, buf ^ 1, tid);

        const float* tb = tiles + buf * 8192;
        if (warp < rows) {
            const float4* trow = (const float4*)(tb + warp * 1024);
            const float4* qrow = (const float4*)q_s;
            float e = 0.f;
#pragma unroll
            for (int j = 0; j < 8; j++) {
                float4 t = trow[lane + 32 * j];
                float4 q4 = qrow[lane + 32 * j];
                e += t.x * q4.x + t.y * q4.y + t.z * q4.z + t.w * q4.w;
            }
#pragma unroll
            for (int o = 16; o; o >>= 1) e += __shfl_xor_sync(0xffffffffu, e, o);
            if (lane == 0) e_chunk[warp] = e;
        }
        __syncthreads();

        float cm = -INFINITY;
        for (int i = 0; i < rows; i++) cm = fmaxf(cm, e_chunk[i]);
        float m_new = fmaxf(m, cm);
        float scale = (m == -INFINITY) ? 0.f : __expf(m - m_new);
        float pr[8];
        float lsum = 0.f;
#pragma unroll
        for (int i = 0; i < 8; i++) {
            pr[i] = (i < rows) ? __expf(e_chunk[i] - m_new) : 0.f;
            lsum += pr[i];
        }
        l = l * scale + lsum;
#pragma unroll
        for (int c = 0; c < 4; c++) {
            float a = acc[c] * scale;
#pragma unroll
            for (int i = 0; i < 8; i++) a += pr[i] * tb[i * 1024 + tid + 256 * c];
            acc[c] = a;
        }
        m = m_new;
        if (tid < rows) g_e[(size_t)b * S_ + s0 + tid] = e_chunk[tid];
        buf ^= 1;
    }

    if (tid == 0) { g_pm[b * NPART + p] = m; g_pl[b * NPART + p] = l; }
#pragma unroll
    for (int c = 0; c < 4; c++)
        g_pacc[((size_t)(b * NPART + p)) * H_ + tid + 256 * c] = acc[c];
}

__global__ void attn_comb_kernel(const int* __restrict__ lens,
                                 float* __restrict__ out_ctx,
                                 float* __restrict__ out_w)
{
    const int b = blockIdx.x;
    const int tid = threadIdx.x;

    float mp[NPART], lp[NPART];
    float m = -INFINITY;
#pragma unroll
    for (int p = 0; p < NPART; p++) {
        mp[p] = g_pm[b * NPART + p];
        lp[p] = g_pl[b * NPART + p];
        m = fmaxf(m, mp[p]);
    }
    float sc[NPART];
    float l = 0.f;
#pragma unroll
    for (int p = 0; p < NPART; p++) {
        sc[p] = (lp[p] > 0.f) ? __expf(mp[p] - m) : 0.f;
        l += lp[p] * sc[p];
    }
    float invl = 1.f / l;

#pragma unroll
    for (int c = 0; c < 4; c++) {
        int h = tid + 256 * c;
        float v = 0.f;
#pragma unroll
        for (int p = 0; p < NPART; p++)
            v += g_pacc[((size_t)(b * NPART + p)) * H_ + h] * sc[p];
        v *= invl;
        g_hc[(size_t)b * (2 * H_) + H_ + h] = v;
        if (out_ctx) out_ctx[(size_t)b * H_ + h] = v;
    }

    if (out_w) {
        int len = lens[b];
        for (int s = tid; s < S_; s += 256) {
            float w = (s < len) ? __expf(g_e[(size_t)b * S_ + s] - m) * invl : 0.f;
            out_w[(size_t)b * S_ + s] = w;
        }
    }
}

// =====================================================================
// BN two-phase + final projection
// =====================================================================
__global__ void bn_phase1(const float* __restrict__ b1)
{
    const int h = (blockIdx.x & 3) * 256 + threadIdx.x;
    const int bc = blockIdx.x >> 2;
    float bias = b1[h];
    float s = 0.f, s2 = 0.f;
    for (int b = bc * (B_ / BCH); b < (bc + 1) * (B_ / BCH); b++) {
        size_t o = (size_t)b * H_ + h;
        float v = bias;
#pragma unroll
        for (int z = 0; z < 8; z++) v += g_yp[(size_t)z * B_ * H_ + o];
        v = fmaxf(v, 0.f);
        g_y[o] = v;
        s += v;
        s2 += v * v;
    }
    g_bns[bc * H_ + h] = s;
    g_bns2[bc * H_ + h] = s2;
}

__global__ void bn_phase2()
{
    const int h = blockIdx.x * 256 + threadIdx.x;
    float s = 0.f, s2 = 0.f;
#pragma unroll
    for (int bc = 0; bc < BCH; bc++) {
        s += g_bns[bc * H_ + h];
        s2 += g_bns2[bc * H_ + h];
    }
    float mu = s * (1.f / B_);
    float var = fmaxf(s2 * (1.f / B_) - mu * mu, 0.f);
    g_mu[h] = mu;
    g_rstd[h] = rsqrtf(var + EPSBN);
}

__global__ void out_kernel(const float* __restrict__ gamma,
                           const float* __restrict__ beta,
                           const float* __restrict__ W2,
                           const float* __restrict__ b2,
                           float* __restrict__ out)
{
    int b = blockIdx.x, tid = threadIdx.x;
    int warp = tid >> 5, lane = tid & 31;
    __shared__ float red[3][8];
    float s0 = 0.f, s1 = 0.f, s2 = 0.f;
#pragma unroll
    for (int c = 0; c < 4; c++) {
        int hh = tid + 256 * c;
        float y = g_y[(size_t)b * H_ + hh];
        float yn = (y - g_mu[hh]) * g_rstd[hh] * gamma[hh] + beta[hh];
        s0 += yn * W2[hh];
        s1 += yn * W2[H_ + hh];
        s2 += yn * W2[2 * H_ + hh];
    }
#pragma unroll
    for (int o = 16; o; o >>= 1) {
        s0 += __shfl_xor_sync(0xffffffffu, s0, o);
        s1 += __shfl_xor_sync(0xffffffffu, s1, o);
        s2 += __shfl_xor_sync(0xffffffffu, s2, o);
    }
    if (lane == 0) { red[0][warp] = s0; red[1][warp] = s1; red[2][warp] = s2; }
    __syncthreads();
    if (tid < 3) {
        float t = 0.f;
#pragma unroll
        for (int w = 0; w < 8; w++) t += red[tid][w];
        out[b * 3 + tid] = t + b2[tid];
    }
}

// =====================================================================
// launcher
// =====================================================================
extern "C" void kernel_launch(void* const* d_in, const int* in_sizes, int n_in,
                              void* d_out, int out_size)
{
    const float* palette  = (const float*)d_in[0];
    const float* last_ctx = (const float*)d_in[1];
    const float* last_h   = (const float*)d_in[2];
    const float* enc      = (const float*)d_in[3];
    const int*   lens     = (const int*)d_in[4];
    const float* attn_W = (const float*)d_in[6];
    const float* attn_b = (const float*)d_in[7];
    const float* Wih    = (const float*)d_in[8];
    const float* Whh    = (const float*)d_in[9];
    const float* bih    = (const float*)d_in[10];
    const float* bhh    = (const float*)d_in[11];
    const float* W1     = (const float*)d_in[12];
    const float* b1     = (const float*)d_in[13];
    const float* gamma  = (const float*)d_in[14];
    const float* beta   = (const float*)d_in[15];
    const float* W2     = (const float*)d_in[16];
    const float* b2     = (const float*)d_in[17];

    float* out_main = (float*)d_out;
    float* out_ctx = 0;
    float* out_h = 0;
    float* out_w = 0;
    if (out_size >= B_ * 3 + 2 * B_ * H_ + B_ * S_) {
        out_ctx = out_main + B_ * 3;
        out_h   = out_ctx + B_ * H_;
        out_w   = out_h + B_ * H_;
    }

    cudaFuncSetAttribute(gemm_dual, cudaFuncAttributeMaxDynamicSharedMemorySize, GEMM_SMEM);
    cudaFuncSetAttribute(gemm_q,    cudaFuncAttributeMaxDynamicSharedMemorySize, GEMM_SMEM);
    cudaFuncSetAttribute(gemm_y,    cudaFuncAttributeMaxDynamicSharedMemorySize, GEMM_SMEM);
    cudaFuncSetAttribute(attn_part_kernel, cudaFuncAttributeMaxDynamicSharedMemorySize, ATT_SMEM);

    // 1) palette partial product (weights consumed directly by GEMMs now)
    gp_kernel<<<192, 256>>>(palette, Wih);
    // 2) gi/gh split-K 2 (384 CTAs) — fused fp32->bf16 staging
    gemm_dual<<<dim3(3 * H_ / 64, B_ / 128, 4), 128, GEMM_SMEM>>>(
        last_ctx, last_h, Wih, Whh);
    // 3) gates -> h (fp32 g_hc)
    gru_gate_kernel<<<B_ * H_ / 256, 256>>>(last_h, bih, bhh, out_h);
    // 4) q partials (split-K 8, 256 CTAs)
    gemm_q<<<dim3(H_ / 64, B_ / 128, 8), 128, GEMM_SMEM>>>(attn_W);
    // 5) q reduce + normalize
    q_reduce_kernel<<<B_, 256>>>(attn_b);
    // 6) attention (8 partitions, 2-buffer)
    attn_part_kernel<<<dim3(B_, NPART), 256, ATT_SMEM>>>(enc, lens);
    // 7) combine (fp32 ctx -> g_hc)
    attn_comb_kernel<<<B_, 256>>>(lens, out_ctx, out_w);
    // 8) y partials (split-K 8, 256 CTAs)
    gemm_y<<<dim3(H_ / 64, B_ / 128, 8), 128, GEMM_SMEM>>>(W1);
    // 9) BN phases (128 + 4 blocks)
    bn_phase1<<<4 * BCH, 256>>>(b1);
    bn_phase2<<<4, 256>>>();
    // 10) final projection
    out_kernel<<<B_, 256>>>(gamma, beta, W2, b2, out_main);
}

// round 16
// speedup vs baseline: 1.0848x; 1.0848x over previous
#include <cuda_runtime.h>
#include <cuda_bf16.h>
#include <math.h>
#include <cstdint>

#define B_ 256
#define H_ 1024
#define P_ 3
#define S_ 512
#define EPSBN 1e-5f
#define NPART 16
#define BCH 32

// ---------------- static device scratch ----------------
__device__ __align__(16) __nv_bfloat16 g_wih_hi[3 * H_ * H_];
__device__ __align__(16) __nv_bfloat16 g_wih_lo[3 * H_ * H_];
__device__ __align__(16) __nv_bfloat16 g_whh_hi[3 * H_ * H_];
__device__ __align__(16) __nv_bfloat16 g_whh_lo[3 * H_ * H_];
__device__ __align__(16) __nv_bfloat16 g_qw_hi[H_ * H_];
__device__ __align__(16) __nv_bfloat16 g_qw_lo[H_ * H_];
__device__ __align__(16) __nv_bfloat16 g_w1_hi[H_ * 2 * H_];
__device__ __align__(16) __nv_bfloat16 g_w1_lo[H_ * 2 * H_];
__device__ __align__(16) __nv_bfloat16 g_xc_hi[B_ * H_];
__device__ __align__(16) __nv_bfloat16 g_xc_lo[B_ * H_];
__device__ __align__(16) __nv_bfloat16 g_xh_hi[B_ * H_];
__device__ __align__(16) __nv_bfloat16 g_xh_lo[B_ * H_];
__device__ __align__(16) __nv_bfloat16 g_hc_hi[B_ * 2 * H_];
__device__ __align__(16) __nv_bfloat16 g_hc_lo[B_ * 2 * H_];

__device__ float g_gp[B_ * 3 * H_];
__device__ float g_gi[2 * B_ * 3 * H_];
__device__ float g_gh[2 * B_ * 3 * H_];
__device__ float g_qp[8 * B_ * H_];
__device__ float g_qn[B_ * H_];
__device__ float g_yp[8 * B_ * H_];
__device__ float g_y[B_ * H_];
__device__ float g_bns[BCH * H_];
__device__ float g_bns2[BCH * H_];
__device__ float g_mu[H_];
__device__ float g_rstd[H_];
__device__ float g_pm[B_ * NPART];
__device__ float g_pl[B_ * NPART];
__device__ float g_pacc[B_ * NPART * H_];
__device__ float g_e[B_ * S_];

// =====================================================================
// helpers
// =====================================================================
__device__ __forceinline__ void split1(float x, __nv_bfloat16& h, __nv_bfloat16& l)
{
    h = __float2bfloat16(x);
    l = __float2bfloat16(x - __bfloat162float(h));
}

__device__ __forceinline__ uint32_t split2u(float x, float y, uint32_t& lo_bits)
{
    __nv_bfloat16 hx, lx, hy, ly;
    split1(x, hx, lx);
    split1(y, hy, ly);
    __nv_bfloat162 h = __halves2bfloat162(hx, hy);
    __nv_bfloat162 l = __halves2bfloat162(lx, ly);
    lo_bits = *reinterpret_cast<uint32_t*>(&l);
    return *reinterpret_cast<uint32_t*>(&h);
}

__device__ __forceinline__ uint32_t smem_u32(const void* p)
{
    uint32_t a;
    asm("{ .reg .u64 t; cvta.to.shared.u64 t, %1; cvt.u32.u64 %0, t; }"
        : "=r"(a) : "l"(p));
    return a;
}

__device__ __forceinline__ void ldsm_x4(uint32_t* r, uint32_t addr)
{
    asm volatile("ldmatrix.sync.aligned.m8n8.x4.shared.b16 {%0,%1,%2,%3}, [%4];"
        : "=r"(r[0]), "=r"(r[1]), "=r"(r[2]), "=r"(r[3]) : "r"(addr));
}

__device__ __forceinline__ void mma_bf16(float* d, const uint32_t* a, const uint32_t* b)
{
    asm volatile(
        "mma.sync.aligned.m16n8k16.row.col.f32.bf16.bf16.f32 "
        "{%0,%1,%2,%3}, {%4,%5,%6,%7}, {%8,%9}, {%0,%1,%2,%3};"
        : "+f"(d[0]), "+f"(d[1]), "+f"(d[2]), "+f"(d[3])
        : "r"(a[0]), "r"(a[1]), "r"(a[2]), "r"(a[3]), "r"(b[0]), "r"(b[1]));
}

#define CP_ASYNC16(saddr, gptr) \
    asm volatile("cp.async.cg.shared.global [%0], [%1], 16;" \
        :: "r"(saddr), "l"(gptr) : "memory")
#define CP_COMMIT() asm volatile("cp.async.commit_group;" ::: "memory")
#define CP_WAIT0()  asm volatile("cp.async.wait_group 0;" ::: "memory")

// =====================================================================
// mma GEMM core: 128x64 C tile, 128 thr (4 warps, each 64x32 tile),
// BK=32, cp.async double-buffered.
// =====================================================================
#define RST 40
#define A_RSZ (128 * RST * 2)
#define B_RSZ (64 * RST * 2)
#define BUF_SZ (2 * A_RSZ + 2 * B_RSZ)
#define GEMM_SMEM (2 * BUF_SZ)

__device__ void mma_core(
    const __nv_bfloat16* __restrict__ Ahi, const __nv_bfloat16* __restrict__ Alo, int lda,
    const __nv_bfloat16* __restrict__ Bhi, const __nv_bfloat16* __restrict__ Blo, int ldb,
    float* __restrict__ C, int ldc,
    int nchunks, int bm0, int bn0)
{
    extern __shared__ unsigned char sm[];
    const uint32_t sb = smem_u32(sm);

    const int tid = threadIdx.x;
    const int wid = tid >> 5, lane = tid & 31;
    const int wm = (wid >> 1) * 64;
    const int wn = (wid & 1) * 32;

    const int rs = tid >> 2;
    const int cs = (tid & 3) * 8;

    const __nv_bfloat16* AhP = Ahi + (size_t)(bm0 + rs) * lda + cs;
    const __nv_bfloat16* AlP = Alo + (size_t)(bm0 + rs) * lda + cs;
    const __nv_bfloat16* BhP = Bhi + (size_t)(bn0 + rs) * ldb + cs;
    const __nv_bfloat16* BlP = Blo + (size_t)(bn0 + rs) * ldb + cs;

    const uint32_t so = (uint32_t)(rs * RST + cs) * 2;
    const uint32_t sstep = (uint32_t)(32 * RST * 2);

#define ISSUE(kb, buf) do { \
        const uint32_t s_ = sb + (buf) * BUF_SZ; \
        CP_ASYNC16(s_ + so,             AhP + (kb)); \
        CP_ASYNC16(s_ + so + sstep,     AhP + (kb) + 32 * lda); \
        CP_ASYNC16(s_ + so + 2 * sstep, AhP + (kb) + 64 * lda); \
        CP_ASYNC16(s_ + so + 3 * sstep, AhP + (kb) + 96 * lda); \
        CP_ASYNC16(s_ + A_RSZ + so,             AlP + (kb)); \
        CP_ASYNC16(s_ + A_RSZ + so + sstep,     AlP + (kb) + 32 * lda); \
        CP_ASYNC16(s_ + A_RSZ + so + 2 * sstep, AlP + (kb) + 64 * lda); \
        CP_ASYNC16(s_ + A_RSZ + so + 3 * sstep, AlP + (kb) + 96 * lda); \
        CP_ASYNC16(s_ + 2 * A_RSZ + so,         BhP + (kb)); \
        CP_ASYNC16(s_ + 2 * A_RSZ + so + sstep, BhP + (kb) + 32 * ldb); \
        CP_ASYNC16(s_ + 2 * A_RSZ + B_RSZ + so,         BlP + (kb)); \
        CP_ASYNC16(s_ + 2 * A_RSZ + B_RSZ + so + sstep, BlP + (kb) + 32 * ldb); \
        CP_COMMIT(); \
    } while (0)

    float acc[4][4][4];
#pragma unroll
    for (int i = 0; i < 4; i++)
#pragma unroll
        for (int j = 0; j < 4; j++)
#pragma unroll
            for (int k = 0; k < 4; k++) acc[i][j][k] = 0.f;

    const uint32_t a_off = (uint32_t)(((wm + (lane & 15)) * RST + (lane >> 4) * 8) * 2);
    const uint32_t b_off = (uint32_t)(((wn + ((lane >> 4) << 3) + (lane & 7)) * RST
                                       + ((lane >> 3) & 1) * 8) * 2);
    const uint32_t mstep = (uint32_t)(16 * RST * 2);

    ISSUE(0, 0);

    for (int t = 0; t < nchunks; t++) {
        CP_WAIT0();
        __syncthreads();
        if (t + 1 < nchunks) ISSUE((t + 1) * 32, (t + 1) & 1);

        const uint32_t base = sb + (t & 1) * BUF_SZ;
        const uint32_t aHi = base, aLo = base + A_RSZ;
        const uint32_t bHi = base + 2 * A_RSZ, bLo = bHi + B_RSZ;

#pragma unroll
        for (int kt = 0; kt < 2; kt++) {
            const uint32_t ko = (uint32_t)(kt * 16 * 2);
            uint32_t bh0[4], bh1[4], bl0[4], bl1[4];
            ldsm_x4(bh0, bHi + b_off + ko);
            ldsm_x4(bh1, bHi + b_off + ko + mstep);
            ldsm_x4(bl0, bLo + b_off + ko);
            ldsm_x4(bl1, bLo + b_off + ko + mstep);

#pragma unroll
            for (int mt = 0; mt < 4; mt++) {
                uint32_t ah[4], al[4];
                ldsm_x4(ah, aHi + a_off + ko + mt * mstep);
                ldsm_x4(al, aLo + a_off + ko + mt * mstep);
#pragma unroll
                for (int nn = 0; nn < 4; nn++) {
                    const uint32_t* BH = ((nn < 2) ? bh0 : bh1) + (nn & 1) * 2;
                    const uint32_t* BL = ((nn < 2) ? bl0 : bl1) + (nn & 1) * 2;
                    float* d = acc[mt][nn];
                    mma_bf16(d, ah, BH);
                    mma_bf16(d, ah, BL);
                    mma_bf16(d, al, BH);
                }
            }
        }
        __syncthreads();
    }

    const int er = lane >> 2;
    const int ec = (lane & 3) * 2;
#pragma unroll
    for (int mt = 0; mt < 4; mt++) {
#pragma unroll
        for (int nn = 0; nn < 4; nn++) {
            const int row = bm0 + wm + mt * 16 + er;
            const int col = bn0 + wn + nn * 8 + ec;
            float* d = acc[mt][nn];
            *(float2*)&C[(size_t)row * ldc + col]       = make_float2(d[0], d[1]);
            *(float2*)&C[(size_t)(row + 8) * ldc + col] = make_float2(d[2], d[3]);
        }
    }
#undef ISSUE
}

__global__ void __launch_bounds__(128) gemm_dual()
{
    const int bm0 = blockIdx.y * 128, bn0 = blockIdx.x * 64;
    const int half = blockIdx.z & 1;
    const int which = blockIdx.z >> 1;
    const int ko = half * 512;
    if (which == 0)
        mma_core(g_xc_hi + ko, g_xc_lo + ko, H_,
                 g_wih_hi + ko, g_wih_lo + ko, H_,
                 g_gi + (size_t)half * B_ * 3 * H_, 3 * H_, 16, bm0, bn0);
    else
        mma_core(g_xh_hi + ko, g_xh_lo + ko, H_,
                 g_whh_hi + ko, g_whh_lo + ko, H_,
                 g_gh + (size_t)half * B_ * 3 * H_, 3 * H_, 16, bm0, bn0);
}

__global__ void __launch_bounds__(128) gemm_q()
{
    const int z = blockIdx.z;
    mma_core(g_hc_hi + z * 128, g_hc_lo + z * 128, 2 * H_,
             g_qw_hi + z * 128, g_qw_lo + z * 128, H_,
             g_qp + (size_t)z * B_ * H_, H_, 4,
             blockIdx.y * 128, blockIdx.x * 64);
}

__global__ void __launch_bounds__(128) gemm_y()
{
    const int z = blockIdx.z;
    mma_core(g_hc_hi + z * 256, g_hc_lo + z * 256, 2 * H_,
             g_w1_hi + z * 256, g_w1_lo + z * 256, 2 * H_,
             g_yp + (size_t)z * B_ * H_, H_, 8,
             blockIdx.y * 128, blockIdx.x * 64);
}

// =====================================================================
// one merged pack kernel (8 floats / thread — round-10/13 layout)
// =====================================================================
__global__ void pack_all(const float* __restrict__ Whh,
                         const float* __restrict__ Wih,
                         const float* __restrict__ attn_W,
                         const float* __restrict__ W1,
                         const float* __restrict__ ctx,
                         const float* __restrict__ h0,
                         const float* __restrict__ palette)
{
    const int bi = blockIdx.x;
    if (bi < 1536) {
        size_t off = ((size_t)bi * 256 + threadIdx.x) * 8;
        float4 f0 = *(const float4*)(Whh + off);
        float4 f1 = *(const float4*)(Whh + off + 4);
        uint4 hv, lv;
        hv.x = split2u(f0.x, f0.y, lv.x);
        hv.y = split2u(f0.z, f0.w, lv.y);
        hv.z = split2u(f1.x, f1.y, lv.z);
        hv.w = split2u(f1.z, f1.w, lv.w);
        *(uint4*)(g_whh_hi + off) = hv;
        *(uint4*)(g_whh_lo + off) = lv;
    } else if (bi < 3072) {
        int t = (bi - 1536) * 256 + threadIdx.x;
        int n = t >> 7;
        int kc = (t & 127) * 8;
        const float* p = Wih + (size_t)n * (H_ + P_) + 3 + kc;
        size_t off = (size_t)n * H_ + kc;
        uint4 hv, lv;
        hv.x = split2u(p[0], p[1], lv.x);
        hv.y = split2u(p[2], p[3], lv.y);
        hv.z = split2u(p[4], p[5], lv.z);
        hv.w = split2u(p[6], p[7], lv.w);
        *(uint4*)(g_wih_hi + off) = hv;
        *(uint4*)(g_wih_lo + off) = lv;
    } else if (bi < 4608) {
        const float* src;
        __nv_bfloat16 *hi, *lo;
        size_t off;
        if (bi < 3584) { src = attn_W; hi = g_qw_hi; lo = g_qw_lo; off = ((size_t)(bi - 3072) * 256 + threadIdx.x) * 8; }
        else           { src = W1;     hi = g_w1_hi; lo = g_w1_lo; off = ((size_t)(bi - 3584) * 256 + threadIdx.x) * 8; }
        float4 f0 = *(const float4*)(src + off);
        float4 f1 = *(const float4*)(src + off + 4);
        uint4 hv, lv;
        hv.x = split2u(f0.x, f0.y, lv.x);
        hv.y = split2u(f0.z, f0.w, lv.y);
        hv.z = split2u(f1.x, f1.y, lv.z);
        hv.w = split2u(f1.z, f1.w, lv.w);
        *(uint4*)(hi + off) = hv;
        *(uint4*)(lo + off) = lv;
    } else if (bi < 4736) {
        size_t off = ((size_t)(bi - 4608) * 256 + threadIdx.x) * 8;
        float4 c0 = *(const float4*)(ctx + off);
        float4 c1 = *(const float4*)(ctx + off + 4);
        float4 h0v = *(const float4*)(h0 + off);
        float4 h1v = *(const float4*)(h0 + off + 4);
        uint4 hv, lv;
        hv.x = split2u(c0.x, c0.y, lv.x);
        hv.y = split2u(c0.z, c0.w, lv.y);
        hv.z = split2u(c1.x, c1.y, lv.z);
        hv.w = split2u(c1.z, c1.w, lv.w);
        *(uint4*)(g_xc_hi + off) = hv;
        *(uint4*)(g_xc_lo + off) = lv;
        hv.x = split2u(h0v.x, h0v.y, lv.x);
        hv.y = split2u(h0v.z, h0v.w, lv.y);
        hv.z = split2u(h1v.x, h1v.y, lv.z);
        hv.w = split2u(h1v.z, h1v.w, lv.w);
        *(uint4*)(g_xh_hi + off) = hv;
        *(uint4*)(g_xh_lo + off) = lv;
    } else {
        const int gb = bi - 4736;
        const int nc = gb % 12;
        const int bc = gb / 12;
        __shared__ float w0[256], w1[256], w2[256];
        const int n = nc * 256 + threadIdx.x;
        w0[threadIdx.x] = Wih[(size_t)n * (H_ + P_) + 0];
        w1[threadIdx.x] = Wih[(size_t)n * (H_ + P_) + 1];
        w2[threadIdx.x] = Wih[(size_t)n * (H_ + P_) + 2];
        __syncthreads();
        for (int b = bc * 16; b < bc * 16 + 16; b++) {
            float p0 = palette[b * 3 + 0], p1 = palette[b * 3 + 1], p2 = palette[b * 3 + 2];
            g_gp[(size_t)b * 3 * H_ + n] =
                p0 * w0[threadIdx.x] + p1 * w1[threadIdx.x] + p2 * w2[threadIdx.x];
        }
    }
}

// =====================================================================
// GRU gates
// =====================================================================
__global__ void gru_gate_kernel(const float* __restrict__ h0,
                                const float* __restrict__ bih,
                                const float* __restrict__ bhh,
                                float* __restrict__ out_h)
{
    const size_t PART = (size_t)B_ * 3 * H_;
    int idx = blockIdx.x * 256 + threadIdx.x;
    int b = idx >> 10;
    int j = idx & (H_ - 1);
    size_t base = (size_t)b * (3 * H_);
    float gir = g_gi[base + j]          + g_gi[PART + base + j]          + g_gp[base + j]          + bih[j];
    float giz = g_gi[base + H_ + j]     + g_gi[PART + base + H_ + j]     + g_gp[base + H_ + j]     + bih[H_ + j];
    float gin = g_gi[base + 2 * H_ + j] + g_gi[PART + base + 2 * H_ + j] + g_gp[base + 2 * H_ + j] + bih[2 * H_ + j];
    float ghr = g_gh[base + j]          + g_gh[PART + base + j]          + bhh[j];
    float ghz = g_gh[base + H_ + j]     + g_gh[PART + base + H_ + j]     + bhh[H_ + j];
    float ghn = g_gh[base + 2 * H_ + j] + g_gh[PART + base + 2 * H_ + j] + bhh[2 * H_ + j];
    float r = 1.f / (1.f + __expf(-(gir + ghr)));
    float z = 1.f / (1.f + __expf(-(giz + ghz)));
    float n = tanhf(gin + r * ghn);
    float h = (1.f - z) * n + z * h0[idx];
    __nv_bfloat16 hh, hl;
    split1(h, hh, hl);
    size_t o = (size_t)b * (2 * H_) + j;
    g_hc_hi[o] = hh;
    g_hc_lo[o] = hl;
    if (out_h) out_h[idx] = h;
}

// =====================================================================
// q reduce + L2 normalize
// =====================================================================
__global__ void q_reduce_kernel(const float* __restrict__ attn_b)
{
    const int b = blockIdx.x, tid = threadIdx.x;
    const int warp = tid >> 5, lane = tid & 31;
    __shared__ float red[8];
    float qv[4];
    float ss = 0.f;
#pragma unroll
    for (int c = 0; c < 4; c++) {
        int h = tid + 256 * c;
        size_t o = (size_t)b * H_ + h;
        float q = attn_b[h];
#pragma unroll
        for (int z = 0; z < 8; z++) q += g_qp[(size_t)z * B_ * H_ + o];
        qv[c] = q;
        ss += q * q;
    }
#pragma unroll
    for (int o = 16; o; o >>= 1) ss += __shfl_xor_sync(0xffffffffu, ss, o);
    if (lane == 0) red[warp] = ss;
    __syncthreads();
    float tot = red[0] + red[1] + red[2] + red[3] + red[4] + red[5] + red[6] + red[7];
    float qinv = rsqrtf(tot);
#pragma unroll
    for (int c = 0; c < 4; c++)
        g_qn[(size_t)b * H_ + tid + 256 * c] = qv[c] * qinv;
}

// =====================================================================
// Attention: NPART=16 seq partitions, 2-buffer cp.async
// =====================================================================
#define ATT_SMEM ((1024 + 2 * 8 * 1024) * 4)

__device__ __forceinline__ void att_issue(
    const float* __restrict__ enc, int b, int s0, int rows,
    float* tiles, uint32_t tiles_sb, int buf, int tid)
{
    const int row = tid >> 5;
    const int seg = (tid & 31) * 32;
    float* dstf = tiles + buf * 8192 + row * 1024 + seg;
    if (row < rows) {
        const float* src = enc + ((size_t)(s0 + row) * B_ + b) * H_ + seg;
        const uint32_t dsa = tiles_sb + (uint32_t)(buf * 8192 + row * 1024 + seg) * 4;
#pragma unroll
        for (int j = 0; j < 8; j++)
            CP_ASYNC16(dsa + j * 16, src + j * 4);
    } else {
#pragma unroll
        for (int j = 0; j < 8; j++)
            *(float4*)(dstf + j * 4) = make_float4(0.f, 0.f, 0.f, 0.f);
    }
    CP_COMMIT();
}

__global__ void __launch_bounds__(256) attn_part_kernel(
    const float* __restrict__ enc,
    const int* __restrict__ lens)
{
    const int b = blockIdx.x;
    const int p = blockIdx.y;
    const int tid = threadIdx.x;
    const int warp = tid >> 5, lane = tid & 31;

    extern __shared__ float dyn[];
    float* q_s = dyn;
    float* tiles = dyn + 1024;
    const uint32_t tiles_sb = smem_u32(tiles);
    __shared__ float e_chunk[8];

#pragma unroll
    for (int c = 0; c < 4; c++)
        q_s[tid + 256 * c] = g_qn[(size_t)b * H_ + tid + 256 * c];
    __syncthreads();

    const int len = lens[b];
    const int sbg = p * (S_ / NPART);
    const int se = min(len, sbg + (S_ / NPART));

    float m = -INFINITY, l = 0.f;
    float acc[4] = {0.f, 0.f, 0.f, 0.f};

    if (sbg < se) att_issue(enc, b, sbg, min(8, se - sbg), tiles, tiles_sb, 0, tid);

    int buf = 0;
    for (int s0 = sbg; s0 < se; s0 += 8) {
        const int rows = min(8, se - s0);
        CP_WAIT0();
        __syncthreads();
        if (s0 + 8 < se)
            att_issue(enc, b, s0 + 8, min(8, se - s0 - 8), tiles, tiles_sb, buf ^ 1, tid);

        const float* tb = tiles + buf * 8192;
        if (warp < rows) {
            const float4* trow = (const float4*)(tb + warp * 1024);
            const float4* qrow = (const float4*)q_s;
            float e = 0.f;
#pragma unroll
            for (int j = 0; j < 8; j++) {
                float4 t = trow[lane + 32 * j];
                float4 q4 = qrow[lane + 32 * j];
                e += t.x * q4.x + t.y * q4.y + t.z * q4.z + t.w * q4.w;
            }
#pragma unroll
            for (int o = 16; o; o >>= 1) e += __shfl_xor_sync(0xffffffffu, e, o);
            if (lane == 0) e_chunk[warp] = e;
        }
        __syncthreads();

        float cm = -INFINITY;
        for (int i = 0; i < rows; i++) cm = fmaxf(cm, e_chunk[i]);
        float m_new = fmaxf(m, cm);
        float scale = (m == -INFINITY) ? 0.f : __expf(m - m_new);
        float pr[8];
        float lsum = 0.f;
#pragma unroll
        for (int i = 0; i < 8; i++) {
            pr[i] = (i < rows) ? __expf(e_chunk[i] - m_new) : 0.f;
            lsum += pr[i];
        }
        l = l * scale + lsum;
#pragma unroll
        for (int c = 0; c < 4; c++) {
            float a = acc[c] * scale;
#pragma unroll
            for (int i = 0; i < 8; i++) a += pr[i] * tb[i * 1024 + tid + 256 * c];
            acc[c] = a;
        }
        m = m_new;
        if (tid < rows) g_e[(size_t)b * S_ + s0 + tid] = e_chunk[tid];
        buf ^= 1;
    }

    if (tid == 0) { g_pm[b * NPART + p] = m; g_pl[b * NPART + p] = l; }
#pragma unroll
    for (int c = 0; c < 4; c++)
        g_pacc[((size_t)(b * NPART + p)) * H_ + tid + 256 * c] = acc[c];
}

__global__ void attn_comb_kernel(const int* __restrict__ lens,
                                 float* __restrict__ out_ctx,
                                 float* __restrict__ out_w)
{
    const int b = blockIdx.x;
    const int tid = threadIdx.x;

    float mp[NPART], lp[NPART];
    float m = -INFINITY;
#pragma unroll
    for (int p = 0; p < NPART; p++) {
        mp[p] = g_pm[b * NPART + p];
        lp[p] = g_pl[b * NPART + p];
        m = fmaxf(m, mp[p]);
    }
    float sc[NPART];
    float l = 0.f;
#pragma unroll
    for (int p = 0; p < NPART; p++) {
        sc[p] = (lp[p] > 0.f) ? __expf(mp[p] - m) : 0.f;
        l += lp[p] * sc[p];
    }
    float invl = 1.f / l;

#pragma unroll
    for (int c = 0; c < 4; c++) {
        int h = tid + 256 * c;
        float v = 0.f;
#pragma unroll
        for (int p = 0; p < NPART; p++)
            v += g_pacc[((size_t)(b * NPART + p)) * H_ + h] * sc[p];
        v *= invl;
        __nv_bfloat16 vh, vl;
        split1(v, vh, vl);
        size_t o = (size_t)b * (2 * H_) + H_ + h;
        g_hc_hi[o] = vh;
        g_hc_lo[o] = vl;
        if (out_ctx) out_ctx[(size_t)b * H_ + h] = v;
    }

    if (out_w) {
        int len = lens[b];
        for (int s = tid; s < S_; s += 256) {
            float w = (s < len) ? __expf(g_e[(size_t)b * S_ + s] - m) * invl : 0.f;
            out_w[(size_t)b * S_ + s] = w;
        }
    }
}

// =====================================================================
// BN two-phase + final projection
// =====================================================================
__global__ void bn_phase1(const float* __restrict__ b1)
{
    const int h = (blockIdx.x & 3) * 256 + threadIdx.x;
    const int bc = blockIdx.x >> 2;
    float bias = b1[h];
    float s = 0.f, s2 = 0.f;
    for (int b = bc * (B_ / BCH); b < (bc + 1) * (B_ / BCH); b++) {
        size_t o = (size_t)b * H_ + h;
        float v = bias;
#pragma unroll
        for (int z = 0; z < 8; z++) v += g_yp[(size_t)z * B_ * H_ + o];
        v = fmaxf(v, 0.f);
        g_y[o] = v;
        s += v;
        s2 += v * v;
    }
    g_bns[bc * H_ + h] = s;
    g_bns2[bc * H_ + h] = s2;
}

__global__ void bn_phase2()
{
    const int h = blockIdx.x * 256 + threadIdx.x;
    float s = 0.f, s2 = 0.f;
#pragma unroll
    for (int bc = 0; bc < BCH; bc++) {
        s += g_bns[bc * H_ + h];
        s2 += g_bns2[bc * H_ + h];
    }
    float mu = s * (1.f / B_);
    float var = fmaxf(s2 * (1.f / B_) - mu * mu, 0.f);
    g_mu[h] = mu;
    g_rstd[h] = rsqrtf(var + EPSBN);
}

__global__ void out_kernel(const float* __restrict__ gamma,
                           const float* __restrict__ beta,
                           const float* __restrict__ W2,
                           const float* __restrict__ b2,
                           float* __restrict__ out)
{
    int b = blockIdx.x, tid = threadIdx.x;
    int warp = tid >> 5, lane = tid & 31;
    __shared__ float red[3][8];
    float s0 = 0.f, s1 = 0.f, s2 = 0.f;
#pragma unroll
    for (int c = 0; c < 4; c++) {
        int hh = tid + 256 * c;
        float y = g_y[(size_t)b * H_ + hh];
        float yn = (y - g_mu[hh]) * g_rstd[hh] * gamma[hh] + beta[hh];
        s0 += yn * W2[hh];
        s1 += yn * W2[H_ + hh];
        s2 += yn * W2[2 * H_ + hh];
    }
#pragma unroll
    for (int o = 16; o; o >>= 1) {
        s0 += __shfl_xor_sync(0xffffffffu, s0, o);
        s1 += __shfl_xor_sync(0xffffffffu, s1, o);
        s2 += __shfl_xor_sync(0xffffffffu, s2, o);
    }
    if (lane == 0) { red[0][warp] = s0; red[1][warp] = s1; red[2][warp] = s2; }
    __syncthreads();
    if (tid < 3) {
        float t = 0.f;
#pragma unroll
        for (int w = 0; w < 8; w++) t += red[tid][w];
        out[b * 3 + tid] = t + b2[tid];
    }
}

// =====================================================================
// launcher
// =====================================================================
extern "C" void kernel_launch(void* const* d_in, const int* in_sizes, int n_in,
                              void* d_out, int out_size)
{
    const float* palette  = (const float*)d_in[0];
    const float* last_ctx = (const float*)d_in[1];
    const float* last_h   = (const float*)d_in[2];
    const float* enc      = (const float*)d_in[3];
    const int*   lens     = (const int*)d_in[4];
    const float* attn_W = (const float*)d_in[6];
    const float* attn_b = (const float*)d_in[7];
    const float* Wih    = (const float*)d_in[8];
    const float* Whh    = (const float*)d_in[9];
    const float* bih    = (const float*)d_in[10];
    const float* bhh    = (const float*)d_in[11];
    const float* W1     = (const float*)d_in[12];
    const float* b1     = (const float*)d_in[13];
    const float* gamma  = (const float*)d_in[14];
    const float* beta   = (const float*)d_in[15];
    const float* W2     = (const float*)d_in[16];
    const float* b2     = (const float*)d_in[17];

    float* out_main = (float*)d_out;
    float* out_ctx = 0;
    float* out_h = 0;
    float* out_w = 0;
    if (out_size >= B_ * 3 + 2 * B_ * H_ + B_ * S_) {
        out_ctx = out_main + B_ * 3;
        out_h   = out_ctx + B_ * H_;
        out_w   = out_h + B_ * H_;
    }

    cudaFuncSetAttribute(gemm_dual, cudaFuncAttributeMaxDynamicSharedMemorySize, GEMM_SMEM);
    cudaFuncSetAttribute(gemm_q,    cudaFuncAttributeMaxDynamicSharedMemorySize, GEMM_SMEM);
    cudaFuncSetAttribute(gemm_y,    cudaFuncAttributeMaxDynamicSharedMemorySize, GEMM_SMEM);
    cudaFuncSetAttribute(attn_part_kernel, cudaFuncAttributeMaxDynamicSharedMemorySize, ATT_SMEM);

    // 1) all packs in one launch (8 floats/thread, 4928 blocks)
    pack_all<<<4928, 256>>>(Whh, Wih, attn_W, W1, last_ctx, last_h, palette);
    // 2) gi/gh split-K 2 (384 CTAs)
    gemm_dual<<<dim3(3 * H_ / 64, B_ / 128, 4), 128, GEMM_SMEM>>>();
    // 3) gates -> h
    gru_gate_kernel<<<B_ * H_ / 256, 256>>>(last_h, bih, bhh, out_h);
    // 4) q partials (split-K 8, 256 CTAs)
    gemm_q<<<dim3(H_ / 64, B_ / 128, 8), 128, GEMM_SMEM>>>();
    // 5) q reduce + normalize
    q_reduce_kernel<<<B_, 256>>>(attn_b);
    // 6) attention (16 partitions, 4096 blocks, 2-buffer)
    attn_part_kernel<<<dim3(B_, NPART), 256, ATT_SMEM>>>(enc, lens);
    // 7) combine (16 partials)
    attn_comb_kernel<<<B_, 256>>>(lens, out_ctx, out_w);
    // 8) y partials (split-K 8, 256 CTAs)
    gemm_y<<<dim3(H_ / 64, B_ / 128, 8), 128, GEMM_SMEM>>>();
    // 9) BN phases (128 + 4 blocks)
    bn_phase1<<<4 * BCH, 256>>>(b1);
    bn_phase2<<<4, 256>>>();
    // 10) final projection
    out_kernel<<<B_, 256>>>(gamma, beta, W2, b2, out_main);
}